// round 2
// baseline (speedup 1.0000x reference)
#include <cuda_runtime.h>
#include <math.h>

#define BB 8
#define TT 2048
#define DD 1024
#define FFN 1024
#define ROWS (BB*TT)                 // 16384
#define NELEM ((size_t)ROWS*DD)      // 16777216

// 8 scratch buffers of 64MB each (512MB total, static device allocation)
__device__ float g_buf[8ull * 16777216ull];
__device__ float g_gx[BB * DD];
__device__ float g_mean[BB];

// ---------------------------------------------------------------------------
// LayerNorm over last dim (D=1024), block = 256 threads, one block per row
// ---------------------------------------------------------------------------
__global__ __launch_bounds__(256) void ln_kernel(
    const float* __restrict__ x, const float* __restrict__ w,
    const float* __restrict__ b, float* __restrict__ out)
{
    int row = blockIdx.x;
    const float* xr = x + (size_t)row * DD;
    float* orow = out + (size_t)row * DD;
    float v[4];
    float s = 0.f, ss = 0.f;
#pragma unroll
    for (int i = 0; i < 4; i++) {
        v[i] = xr[threadIdx.x + i * 256];
        s += v[i];
        ss += v[i] * v[i];
    }
#pragma unroll
    for (int o = 16; o > 0; o >>= 1) {
        s  += __shfl_xor_sync(0xffffffffu, s,  o);
        ss += __shfl_xor_sync(0xffffffffu, ss, o);
    }
    __shared__ float reds[8], redss[8];
    __shared__ float smean, sinv;
    int warp = threadIdx.x >> 5, lane = threadIdx.x & 31;
    if (lane == 0) { reds[warp] = s; redss[warp] = ss; }
    __syncthreads();
    if (threadIdx.x == 0) {
        float ts = 0.f, tss = 0.f;
#pragma unroll
        for (int i = 0; i < 8; i++) { ts += reds[i]; tss += redss[i]; }
        float mean = ts * (1.f / 1024.f);
        float var = tss * (1.f / 1024.f) - mean * mean;
        smean = mean;
        sinv = rsqrtf(var + 1e-5f);
    }
    __syncthreads();
    float mean = smean, inv = sinv;
#pragma unroll
    for (int i = 0; i < 4; i++) {
        int c = threadIdx.x + i * 256;
        orow[c] = (v[i] - mean) * inv * w[c] + b[c];
    }
}

// ---------------------------------------------------------------------------
// xm = 0.5 * (xx[t] + xx[t-1]); xx[-1] = 0 per batch element
// ---------------------------------------------------------------------------
__global__ void xm_kernel(const float* __restrict__ xx, float* __restrict__ xm)
{
    size_t idx = (size_t)blockIdx.x * blockDim.x + threadIdx.x;
    if (idx >= NELEM) return;
    size_t row = idx >> 10;
    int tl = (int)(row & 2047);
    float prev = tl ? xx[idx - DD] : 0.f;
    xm[idx] = 0.5f * (xx[idx] + prev);
}

// ---------------------------------------------------------------------------
// SGEMM: C[M,N] = A[M,K] @ B[K,N] (+ epilogue). Row-major. 128x128x8 tiles.
// ---------------------------------------------------------------------------
enum { EPI_NONE = 0, EPI_RESID = 1, EPI_BIAS = 2, EPI_BIAS_RELU2 = 3, EPI_BIAS_SIG = 4 };

template <int EPI>
__global__ __launch_bounds__(256) void sgemm_kernel(
    const float* __restrict__ A, const float* __restrict__ B,
    float* __restrict__ C, const float* __restrict__ X,
    int M, int N, int K)
{
    __shared__ float As[8][128];
    __shared__ float Bs[8][128];
    const int tid = threadIdx.x;
    const int bx = blockIdx.x, by = blockIdx.y;
    const int arow = tid >> 1, acol = (tid & 1) << 2;
    const int brow = tid >> 5, bcol = (tid & 31) << 2;
    const int tx = tid & 15, ty = tid >> 4;
    const float* Ap = A + (size_t)(by * 128 + arow) * K + acol;
    const float* Bp = B + (size_t)brow * N + bx * 128 + bcol;

    float acc[8][8];
#pragma unroll
    for (int i = 0; i < 8; i++)
#pragma unroll
        for (int j = 0; j < 8; j++) acc[i][j] = 0.f;

    for (int k0 = 0; k0 < K; k0 += 8) {
        float4 av = *(const float4*)(Ap + k0);
        float4 bv = *(const float4*)(Bp + (size_t)k0 * N);
        As[acol + 0][arow] = av.x;
        As[acol + 1][arow] = av.y;
        As[acol + 2][arow] = av.z;
        As[acol + 3][arow] = av.w;
        *(float4*)&Bs[brow][bcol] = bv;
        __syncthreads();
#pragma unroll
        for (int k = 0; k < 8; k++) {
            float a[8], b[8];
            *(float4*)(a)     = *(const float4*)&As[k][ty * 8];
            *(float4*)(a + 4) = *(const float4*)&As[k][ty * 8 + 4];
            *(float4*)(b)     = *(const float4*)&Bs[k][tx * 8];
            *(float4*)(b + 4) = *(const float4*)&Bs[k][tx * 8 + 4];
#pragma unroll
            for (int i = 0; i < 8; i++)
#pragma unroll
                for (int j = 0; j < 8; j++)
                    acc[i][j] = fmaf(a[i], b[j], acc[i][j]);
        }
        __syncthreads();
    }

#pragma unroll
    for (int i = 0; i < 8; i++) {
        size_t row = (size_t)by * 128 + ty * 8 + i;
        size_t base = row * N + bx * 128 + tx * 8;
#pragma unroll
        for (int j = 0; j < 8; j++) {
            float val = acc[i][j];
            int col = bx * 128 + tx * 8 + j;
            if (EPI == EPI_RESID) {
                val += X[base + j];
            } else if (EPI == EPI_BIAS) {
                val += X[col];
            } else if (EPI == EPI_BIAS_RELU2) {
                float t = val + X[col];
                t = t > 0.f ? t : 0.f;
                val = t * t;
            } else if (EPI == EPI_BIAS_SIG) {
                float t = val + X[col];
                val = 1.f / (1.f + expf(-t));
            }
            C[base + j] = val;
        }
    }
}

// ---------------------------------------------------------------------------
// fuse1: u = k*v + a*b (in place on k), rg = sigmoid(r)*sigmoid(g) (in place on r)
// ---------------------------------------------------------------------------
__global__ void fuse1_kernel(
    const float* __restrict__ r, const float* __restrict__ g,
    const float* __restrict__ k, const float* __restrict__ v,
    const float* __restrict__ a, const float* __restrict__ b,
    float* __restrict__ u, float* __restrict__ rg)
{
    size_t idx = (size_t)blockIdx.x * blockDim.x + threadIdx.x;
    if (idx >= NELEM) return;
    float kv = k[idx] * v[idx];
    float ab = a[idx] * b[idx];
    float sr = 1.f / (1.f + expf(-r[idx]));
    float sg = 1.f / (1.f + expf(-g[idx]));
    u[idx] = kv + ab;
    rg[idx] = sr * sg;
}

// ---------------------------------------------------------------------------
// Sequential decay scan over time per (b,d)
// ---------------------------------------------------------------------------
__global__ void scan_kernel(
    const float* __restrict__ u, const float* __restrict__ state0,
    const float* __restrict__ decay, float* __restrict__ states,
    float* __restrict__ final_state)
{
    int tid = blockIdx.x * blockDim.x + threadIdx.x;  // 8192
    int bb = tid >> 10, d = tid & 1023;
    float w = expf(-expf(decay[d]));
    float s = state0[tid];
    size_t idx = (size_t)bb * TT * DD + d;
    for (int t = 0; t < TT; t++, idx += DD) {
        s = fmaf(s, w, u[idx]);
        states[idx] = s;
    }
    final_state[tid] = s;
}

// ---------------------------------------------------------------------------
// GroupNorm(32 groups of 32) over states, fused multiply by rg
// ---------------------------------------------------------------------------
__global__ __launch_bounds__(256) void gnorm_kernel(
    const float* __restrict__ states, const float* __restrict__ rg,
    const float* __restrict__ gw, const float* __restrict__ gb,
    float* __restrict__ out)
{
    int row = blockIdx.x;
    int warp = threadIdx.x >> 5, lane = threadIdx.x & 31;
    size_t base = (size_t)row * DD;
#pragma unroll
    for (int g = warp; g < 32; g += 8) {
        int c = g * 32 + lane;
        float v = states[base + c];
        float s = v, ss = v * v;
#pragma unroll
        for (int o = 16; o > 0; o >>= 1) {
            s  += __shfl_xor_sync(0xffffffffu, s,  o);
            ss += __shfl_xor_sync(0xffffffffu, ss, o);
        }
        float mean = s * (1.f / 32.f);
        float var = ss * (1.f / 32.f) - mean * mean;
        float inv = rsqrtf(var + 1e-5f);
        out[base + c] = ((v - mean) * inv * gw[c] + gb[c]) * rg[base + c];
    }
}

// ---------------------------------------------------------------------------
// GRN: gx[b,d] = sqrt(sum_t h^2)
// ---------------------------------------------------------------------------
__global__ void grn_gx_kernel(const float* __restrict__ h, float* __restrict__ gx)
{
    int tid = blockIdx.x * blockDim.x + threadIdx.x;  // 8192
    int bb = tid >> 10, d = tid & 1023;
    size_t idx = (size_t)bb * TT * DD + d;
    float s = 0.f;
    for (int t = 0; t < TT; t++, idx += DD) {
        float v = h[idx];
        s = fmaf(v, v, s);
    }
    gx[tid] = sqrtf(s);
}

__global__ __launch_bounds__(256) void grn_mean_kernel(
    const float* __restrict__ gx, float* __restrict__ mean)
{
    int b = blockIdx.x;
    float s = 0.f;
    for (int i = threadIdx.x; i < DD; i += 256) s += gx[b * DD + i];
#pragma unroll
    for (int o = 16; o > 0; o >>= 1) s += __shfl_xor_sync(0xffffffffu, s, o);
    __shared__ float red[8];
    int warp = threadIdx.x >> 5, lane = threadIdx.x & 31;
    if (lane == 0) red[warp] = s;
    __syncthreads();
    if (threadIdx.x == 0) {
        float t = 0.f;
#pragma unroll
        for (int i = 0; i < 8; i++) t += red[i];
        mean[b] = t * (1.f / 1024.f);
    }
}

// ---------------------------------------------------------------------------
// pre2 = fr * (gamma*(h*nx) + beta + h),  nx = gx / (mean + 1e-6)
// ---------------------------------------------------------------------------
__global__ void pre2_kernel(
    const float* __restrict__ fr, const float* __restrict__ h,
    const float* __restrict__ gx, const float* __restrict__ mean,
    const float* __restrict__ gamma, const float* __restrict__ beta,
    float* __restrict__ out)
{
    size_t idx = (size_t)blockIdx.x * blockDim.x + threadIdx.x;
    if (idx >= NELEM) return;
    int d = (int)(idx & 1023);
    size_t row = idx >> 10;
    int bb = (int)(row >> 11);  // row / 2048
    float nx = gx[bb * DD + d] / (mean[bb] + 1e-6f);
    float hv = h[idx];
    float hidden = fmaf(hv, gamma[d] * nx, beta[d]) + hv;
    out[idx] = fr[idx] * hidden;
}

// ---------------------------------------------------------------------------
// launch
// ---------------------------------------------------------------------------
extern "C" void kernel_launch(void* const* d_in, const int* in_sizes, int n_in,
                              void* d_out, int out_size)
{
    const float* x       = (const float*)d_in[0];
    const float* state   = (const float*)d_in[1];
    const float* ln1_w   = (const float*)d_in[2];
    const float* ln1_b   = (const float*)d_in[3];
    const float* ln2_w   = (const float*)d_in[4];
    const float* ln2_b   = (const float*)d_in[5];
    const float* gn_w    = (const float*)d_in[6];
    const float* gn_b    = (const float*)d_in[7];
    const float* grn_g   = (const float*)d_in[8];
    const float* grn_b   = (const float*)d_in[9];
    const float* decay   = (const float*)d_in[10];
    const float* Wr      = (const float*)d_in[11];
    const float* Wk      = (const float*)d_in[12];
    const float* Wv      = (const float*)d_in[13];
    const float* Wg      = (const float*)d_in[14];
    const float* Wa      = (const float*)d_in[15];
    const float* Wb      = (const float*)d_in[16];
    const float* Wout    = (const float*)d_in[17];
    const float* Wffnout = (const float*)d_in[18];
    const float* Wfk     = (const float*)d_in[19];
    const float* bfk     = (const float*)d_in[20];
    const float* Wfv     = (const float*)d_in[21];
    const float* bfv     = (const float*)d_in[22];
    const float* Wfr     = (const float*)d_in[23];
    const float* bfr     = (const float*)d_in[24];

    float* out_x = (float*)d_out;
    float* out_state = out_x + NELEM;

    float* buf;
    cudaGetSymbolAddress((void**)&buf, g_buf);
    float* gxp;
    cudaGetSymbolAddress((void**)&gxp, g_gx);
    float* meanp;
    cudaGetSymbolAddress((void**)&meanp, g_mean);

    float* B0 = buf + 0ull * NELEM;  // xx    -> kffn
    float* B1 = buf + 1ull * NELEM;  // xm    -> h
    float* B2 = buf + 2ull * NELEM;  // r     -> rg    -> fr
    float* B3 = buf + 3ull * NELEM;  // k     -> u     -> pre2
    float* B4 = buf + 4ull * NELEM;  // v     -> states
    float* B5 = buf + 5ull * NELEM;  // a     -> pre1
    float* B6 = buf + 6ull * NELEM;  // b     -> x2
    float* B7 = buf + 7ull * NELEM;  // g     -> xx2

    const int grid_e = (int)(NELEM / 256);  // 65536
    dim3 gg(DD / 128, ROWS / 128);          // (8, 128)

    // 1. LN1 + time mix
    ln_kernel<<<ROWS, 256>>>(x, ln1_w, ln1_b, B0);
    xm_kernel<<<grid_e, 256>>>(B0, B1);

    // 2. six projections
    sgemm_kernel<EPI_NONE><<<gg, 256>>>(B1, Wr, B2, nullptr, ROWS, DD, DD);
    sgemm_kernel<EPI_NONE><<<gg, 256>>>(B1, Wk, B3, nullptr, ROWS, DD, DD);
    sgemm_kernel<EPI_NONE><<<gg, 256>>>(B1, Wv, B4, nullptr, ROWS, DD, DD);
    sgemm_kernel<EPI_NONE><<<gg, 256>>>(B1, Wg, B7, nullptr, ROWS, DD, DD);
    sgemm_kernel<EPI_NONE><<<gg, 256>>>(B1, Wa, B5, nullptr, ROWS, DD, DD);
    sgemm_kernel<EPI_NONE><<<gg, 256>>>(B1, Wb, B6, nullptr, ROWS, DD, DD);

    // 3. u = k*v + a*b, rg = sigmoid(r)*sigmoid(g)
    fuse1_kernel<<<grid_e, 256>>>(B2, B7, B3, B4, B5, B6, B3, B2);

    // 4. decay scan (also writes final state to output tail)
    scan_kernel<<<32, 256>>>(B3, state, decay, B4, out_state);

    // 5. GroupNorm * rg
    gnorm_kernel<<<ROWS, 256>>>(B4, B2, gn_w, gn_b, B5);

    // 6. mixed projection + residual -> x2
    sgemm_kernel<EPI_RESID><<<gg, 256>>>(B5, Wout, B6, x, ROWS, DD, DD);

    // 7. LN2
    ln_kernel<<<ROWS, 256>>>(B6, ln2_w, ln2_b, B7);

    // 8. FFN key: relu^2(xx2 @ Wfk + bfk)
    sgemm_kernel<EPI_BIAS_RELU2><<<gg, 256>>>(B7, Wfk, B0, bfk, ROWS, FFN, DD);

    // 9. h = kffn @ Wfv + bfv
    sgemm_kernel<EPI_BIAS><<<gg, 256>>>(B0, Wfv, B1, bfv, ROWS, DD, FFN);

    // 10. fr = sigmoid(xx2 @ Wfr + bfr)
    sgemm_kernel<EPI_BIAS_SIG><<<gg, 256>>>(B7, Wfr, B2, bfr, ROWS, DD, DD);

    // 11. GRN stats
    grn_gx_kernel<<<32, 256>>>(B1, gxp);
    grn_mean_kernel<<<8, 256>>>(gxp, meanp);

    // 12. pre2 = fr * ffn_hidden
    pre2_kernel<<<grid_e, 256>>>(B2, B1, gxp, meanp, grn_g, grn_b, B3);

    // 13. final projection + residual -> output x
    sgemm_kernel<EPI_RESID><<<gg, 256>>>(B3, Wffnout, out_x, B6, ROWS, DD, DD);
}

// round 4
// speedup vs baseline: 3.2817x; 3.2817x over previous
#include <cuda_runtime.h>
#include <math.h>
#include <stdint.h>

#define BB 8
#define TT 2048
#define DD 1024
#define FFN 1024
#define ROWS (BB*TT)                 // 16384
#define NELEM ((size_t)ROWS*DD)      // 16777216

// 8 scratch buffers of 64MB each (512MB total, static device allocation)
__device__ float g_buf[8ull * 16777216ull];
__device__ float g_gx[BB * DD];
__device__ float g_mean[BB];

// ===========================================================================
// helpers
// ===========================================================================
__device__ __forceinline__ uint32_t smem_u32(const void* p) {
    uint32_t a;
    asm("{ .reg .u64 t; cvta.to.shared.u64 t, %1; cvt.u32.u64 %0, t; }"
        : "=r"(a) : "l"(p));
    return a;
}

__device__ __forceinline__ void cp16(uint32_t dst, const void* src) {
    asm volatile("cp.async.cg.shared.global [%0], [%1], 16;"
                 :: "r"(dst), "l"(src));
}

__device__ __forceinline__ uint32_t f2tf(float x) {
    uint32_t y;
    asm("cvt.rna.tf32.f32 %0, %1;" : "=r"(y) : "f"(x));
    return y;
}

__device__ __forceinline__ void mma8(float* d, const uint32_t* a,
                                     uint32_t b0, uint32_t b1) {
    asm("mma.sync.aligned.m16n8k8.row.col.f32.tf32.tf32.f32 "
        "{%0,%1,%2,%3}, {%4,%5,%6,%7}, {%8,%9}, {%0,%1,%2,%3};"
        : "+f"(d[0]), "+f"(d[1]), "+f"(d[2]), "+f"(d[3])
        : "r"(a[0]), "r"(a[1]), "r"(a[2]), "r"(a[3]), "r"(b0), "r"(b1));
}

// ===========================================================================
// tf32 mma.sync GEMM: C[M,N] = A[M,K] @ W[K,N] (+ epilogue)
// CTA tile 128M x 256N, k-stage 32, 3-stage cp.async pipeline, 256 threads.
// Warps 2(m) x 4(n); warp tile 64x64; mma m16n8k8.
// ===========================================================================
enum { EPI_NONE = 0, EPI_RESID = 1, EPI_BIAS = 2, EPI_BIAS_RELU2 = 3, EPI_BIAS_SIG = 4 };

#define A_ST 4096            // floats per A stage (128x32)
#define B_ST 8192            // floats per B stage (32x256)
#define GEMM_SMEM 147456     // 3*(A_ST+B_ST)*4 bytes

__device__ __forceinline__ void load_stage(
    const float* __restrict__ A, const float* __restrict__ W,
    int K, int N, int m0, int n0, uint32_t a_base, uint32_t b_base,
    int kc, int tid)
{
    // A tile: 128 rows x 32 k; 1024 16B chunks; swizzle chunk k4 ^ (m&7)
#pragma unroll
    for (int i = 0; i < 4; ++i) {
        int chunk = i * 256 + tid;
        int m = chunk >> 3, k4 = chunk & 7;
        const float* src = A + (size_t)(m0 + m) * K + kc + k4 * 4;
        cp16(a_base + (uint32_t)(m * 8 + (k4 ^ (m & 7))) * 16u, src);
    }
    // B tile: 32 k x 256 n; 2048 chunks; swizzle chunk n4 ^ ((k&3)<<1)
#pragma unroll
    for (int i = 0; i < 8; ++i) {
        int chunk = i * 256 + tid;
        int k = chunk >> 6, n4 = chunk & 63;
        const float* src = W + (size_t)(kc + k) * N + n0 + n4 * 4;
        cp16(b_base + (uint32_t)(k * 64 + (n4 ^ ((k & 3) << 1))) * 16u, src);
    }
    asm volatile("cp.async.commit_group;");
}

template <int EPI>
__global__ __launch_bounds__(256, 1) void mgemm(
    const float* __restrict__ A, const float* __restrict__ W,
    float* __restrict__ C, const float* __restrict__ X,
    int M, int N, int K)
{
    extern __shared__ float sm[];
    float* As = sm;                  // 3 stages x 4096
    float* Bs = sm + 3 * A_ST;       // 3 stages x 8192

    const int tid = threadIdx.x;
    const int w = tid >> 5, lane = tid & 31;
    const int wm = w & 1, wn = w >> 1;
    const int r = lane >> 2, c = lane & 3;
    const int m0 = blockIdx.y * 128;
    const int n0 = blockIdx.x * 256;

    uint32_t a_sb = smem_u32(As);
    uint32_t b_sb = smem_u32(Bs);

    float acc[4][8][4];
#pragma unroll
    for (int mt = 0; mt < 4; ++mt)
#pragma unroll
        for (int nt = 0; nt < 8; ++nt)
#pragma unroll
            for (int i = 0; i < 4; ++i) acc[mt][nt][i] = 0.f;

    const int NCH = K >> 5;   // 32

    load_stage(A, W, K, N, m0, n0, a_sb, b_sb, 0, tid);
    load_stage(A, W, K, N, m0, n0, a_sb + A_ST * 4, b_sb + B_ST * 4, 32, tid);

    for (int ch = 0; ch < NCH; ++ch) {
        asm volatile("cp.async.wait_group 1;");
        __syncthreads();

        const int p = ch % 3;
        const float* Ap = As + p * A_ST;
        const float* Bp = Bs + p * B_ST;

#pragma unroll
        for (int ks = 0; ks < 4; ++ks) {
            const int k0 = ks * 8;
            const int kc0 = (k0 + c) ^ (r << 2);
            const int kc4 = (k0 + c + 4) ^ (r << 2);
            uint32_t a[4][4];
#pragma unroll
            for (int mt = 0; mt < 4; ++mt) {
                int base = (wm * 64 + mt * 16 + r) * 32;
                a[mt][0] = f2tf(Ap[base + kc0]);
                a[mt][1] = f2tf(Ap[base + 256 + kc0]);   // +8 rows
                a[mt][2] = f2tf(Ap[base + kc4]);
                a[mt][3] = f2tf(Ap[base + 256 + kc4]);
            }
#pragma unroll
            for (int nt = 0; nt < 8; ++nt) {
                int nsw = (wn * 64 + nt * 8 + r) ^ (c << 3);
                uint32_t b0 = f2tf(Bp[(k0 + c) * 256 + nsw]);
                uint32_t b1 = f2tf(Bp[(k0 + c + 4) * 256 + nsw]);
#pragma unroll
                for (int mt = 0; mt < 4; ++mt)
                    mma8(acc[mt][nt], a[mt], b0, b1);
            }
        }

        const int nc = ch + 2;
        if (nc < NCH) {
            load_stage(A, W, K, N, m0, n0,
                       a_sb + (uint32_t)(nc % 3) * A_ST * 4,
                       b_sb + (uint32_t)(nc % 3) * B_ST * 4,
                       nc * 32, tid);
        } else {
            asm volatile("cp.async.commit_group;");
        }
    }

    // --- epilogue: direct register -> global stores (32B sectors per quad) ---
#pragma unroll
    for (int mt = 0; mt < 4; ++mt) {
#pragma unroll
        for (int nt = 0; nt < 8; ++nt) {
            int row = m0 + wm * 64 + mt * 16 + r;
            int col = n0 + wn * 64 + nt * 8 + 2 * c;
#pragma unroll
            for (int h = 0; h < 2; ++h) {        // h=0: row, h=1: row+8
                int rr = row + h * 8;
                float v0 = acc[mt][nt][h * 2 + 0];
                float v1 = acc[mt][nt][h * 2 + 1];
                size_t gi = (size_t)rr * N + col;
                if (EPI == EPI_RESID) {
                    v0 += X[gi]; v1 += X[gi + 1];
                } else if (EPI == EPI_BIAS) {
                    v0 += X[col]; v1 += X[col + 1];
                } else if (EPI == EPI_BIAS_RELU2) {
                    float t0 = v0 + X[col];     t0 = t0 > 0.f ? t0 : 0.f;
                    float t1 = v1 + X[col + 1]; t1 = t1 > 0.f ? t1 : 0.f;
                    v0 = t0 * t0; v1 = t1 * t1;
                } else if (EPI == EPI_BIAS_SIG) {
                    v0 = 1.f / (1.f + expf(-(v0 + X[col])));
                    v1 = 1.f / (1.f + expf(-(v1 + X[col + 1])));
                }
                float2 o; o.x = v0; o.y = v1;
                *(float2*)(C + gi) = o;
            }
        }
    }
}

// ===========================================================================
// Non-GEMM kernels (unchanged from passing round-1 kernel)
// ===========================================================================
__global__ __launch_bounds__(256) void ln_kernel(
    const float* __restrict__ x, const float* __restrict__ w,
    const float* __restrict__ b, float* __restrict__ out)
{
    int row = blockIdx.x;
    const float* xr = x + (size_t)row * DD;
    float* orow = out + (size_t)row * DD;
    float v[4];
    float s = 0.f, ss = 0.f;
#pragma unroll
    for (int i = 0; i < 4; i++) {
        v[i] = xr[threadIdx.x + i * 256];
        s += v[i];
        ss += v[i] * v[i];
    }
#pragma unroll
    for (int o = 16; o > 0; o >>= 1) {
        s  += __shfl_xor_sync(0xffffffffu, s,  o);
        ss += __shfl_xor_sync(0xffffffffu, ss, o);
    }
    __shared__ float reds[8], redss[8];
    __shared__ float smean, sinv;
    int warp = threadIdx.x >> 5, lane = threadIdx.x & 31;
    if (lane == 0) { reds[warp] = s; redss[warp] = ss; }
    __syncthreads();
    if (threadIdx.x == 0) {
        float ts = 0.f, tss = 0.f;
#pragma unroll
        for (int i = 0; i < 8; i++) { ts += reds[i]; tss += redss[i]; }
        float mean = ts * (1.f / 1024.f);
        float var = tss * (1.f / 1024.f) - mean * mean;
        smean = mean;
        sinv = rsqrtf(var + 1e-5f);
    }
    __syncthreads();
    float mean = smean, inv = sinv;
#pragma unroll
    for (int i = 0; i < 4; i++) {
        int cc = threadIdx.x + i * 256;
        orow[cc] = (v[i] - mean) * inv * w[cc] + b[cc];
    }
}

__global__ void xm_kernel(const float* __restrict__ xx, float* __restrict__ xm)
{
    size_t idx = (size_t)blockIdx.x * blockDim.x + threadIdx.x;
    if (idx >= NELEM) return;
    size_t row = idx >> 10;
    int tl = (int)(row & 2047);
    float prev = tl ? xx[idx - DD] : 0.f;
    xm[idx] = 0.5f * (xx[idx] + prev);
}

__global__ void fuse1_kernel(
    const float* __restrict__ r, const float* __restrict__ g,
    const float* __restrict__ k, const float* __restrict__ v,
    const float* __restrict__ a, const float* __restrict__ b,
    float* __restrict__ u, float* __restrict__ rg)
{
    size_t idx = (size_t)blockIdx.x * blockDim.x + threadIdx.x;
    if (idx >= NELEM) return;
    float kv = k[idx] * v[idx];
    float ab = a[idx] * b[idx];
    float sr = 1.f / (1.f + expf(-r[idx]));
    float sg = 1.f / (1.f + expf(-g[idx]));
    u[idx] = kv + ab;
    rg[idx] = sr * sg;
}

__global__ void scan_kernel(
    const float* __restrict__ u, const float* __restrict__ state0,
    const float* __restrict__ decay, float* __restrict__ states,
    float* __restrict__ final_state)
{
    int tid = blockIdx.x * blockDim.x + threadIdx.x;  // 8192
    int bb = tid >> 10, d = tid & 1023;
    float w = expf(-expf(decay[d]));
    float s = state0[tid];
    size_t idx = (size_t)bb * TT * DD + d;
    for (int t = 0; t < TT; t++, idx += DD) {
        s = fmaf(s, w, u[idx]);
        states[idx] = s;
    }
    final_state[tid] = s;
}

__global__ __launch_bounds__(256) void gnorm_kernel(
    const float* __restrict__ states, const float* __restrict__ rg,
    const float* __restrict__ gw, const float* __restrict__ gb,
    float* __restrict__ out)
{
    int row = blockIdx.x;
    int warp = threadIdx.x >> 5, lane = threadIdx.x & 31;
    size_t base = (size_t)row * DD;
#pragma unroll
    for (int g = warp; g < 32; g += 8) {
        int cc = g * 32 + lane;
        float v = states[base + cc];
        float s = v, ss = v * v;
#pragma unroll
        for (int o = 16; o > 0; o >>= 1) {
            s  += __shfl_xor_sync(0xffffffffu, s,  o);
            ss += __shfl_xor_sync(0xffffffffu, ss, o);
        }
        float mean = s * (1.f / 32.f);
        float var = ss * (1.f / 32.f) - mean * mean;
        float inv = rsqrtf(var + 1e-5f);
        out[base + cc] = ((v - mean) * inv * gw[cc] + gb[cc]) * rg[base + cc];
    }
}

__global__ void grn_gx_kernel(const float* __restrict__ h, float* __restrict__ gx)
{
    int tid = blockIdx.x * blockDim.x + threadIdx.x;  // 8192
    int bb = tid >> 10, d = tid & 1023;
    size_t idx = (size_t)bb * TT * DD + d;
    float s = 0.f;
    for (int t = 0; t < TT; t++, idx += DD) {
        float v = h[idx];
        s = fmaf(v, v, s);
    }
    gx[tid] = sqrtf(s);
}

__global__ __launch_bounds__(256) void grn_mean_kernel(
    const float* __restrict__ gx, float* __restrict__ mean)
{
    int b = blockIdx.x;
    float s = 0.f;
    for (int i = threadIdx.x; i < DD; i += 256) s += gx[b * DD + i];
#pragma unroll
    for (int o = 16; o > 0; o >>= 1) s += __shfl_xor_sync(0xffffffffu, s, o);
    __shared__ float red[8];
    int warp = threadIdx.x >> 5, lane = threadIdx.x & 31;
    if (lane == 0) red[warp] = s;
    __syncthreads();
    if (threadIdx.x == 0) {
        float t = 0.f;
#pragma unroll
        for (int i = 0; i < 8; i++) t += red[i];
        mean[b] = t * (1.f / 1024.f);
    }
}

__global__ void pre2_kernel(
    const float* __restrict__ fr, const float* __restrict__ h,
    const float* __restrict__ gx, const float* __restrict__ mean,
    const float* __restrict__ gamma, const float* __restrict__ beta,
    float* __restrict__ out)
{
    size_t idx = (size_t)blockIdx.x * blockDim.x + threadIdx.x;
    if (idx >= NELEM) return;
    int d = (int)(idx & 1023);
    size_t row = idx >> 10;
    int bb = (int)(row >> 11);
    float nx = gx[bb * DD + d] / (mean[bb] + 1e-6f);
    float hv = h[idx];
    float hidden = fmaf(hv, gamma[d] * nx, beta[d]) + hv;
    out[idx] = fr[idx] * hidden;
}

// ===========================================================================
// launch
// ===========================================================================
extern "C" void kernel_launch(void* const* d_in, const int* in_sizes, int n_in,
                              void* d_out, int out_size)
{
    const float* x       = (const float*)d_in[0];
    const float* state   = (const float*)d_in[1];
    const float* ln1_w   = (const float*)d_in[2];
    const float* ln1_b   = (const float*)d_in[3];
    const float* ln2_w   = (const float*)d_in[4];
    const float* ln2_b   = (const float*)d_in[5];
    const float* gn_w    = (const float*)d_in[6];
    const float* gn_b    = (const float*)d_in[7];
    const float* grn_g   = (const float*)d_in[8];
    const float* grn_b   = (const float*)d_in[9];
    const float* decay   = (const float*)d_in[10];
    const float* Wr      = (const float*)d_in[11];
    const float* Wk      = (const float*)d_in[12];
    const float* Wv      = (const float*)d_in[13];
    const float* Wg      = (const float*)d_in[14];
    const float* Wa      = (const float*)d_in[15];
    const float* Wb      = (const float*)d_in[16];
    const float* Wout    = (const float*)d_in[17];
    const float* Wffnout = (const float*)d_in[18];
    const float* Wfk     = (const float*)d_in[19];
    const float* bfk     = (const float*)d_in[20];
    const float* Wfv     = (const float*)d_in[21];
    const float* bfv     = (const float*)d_in[22];
    const float* Wfr     = (const float*)d_in[23];
    const float* bfr     = (const float*)d_in[24];

    float* out_x = (float*)d_out;
    float* out_state = out_x + NELEM;

    float* buf;   cudaGetSymbolAddress((void**)&buf, g_buf);
    float* gxp;   cudaGetSymbolAddress((void**)&gxp, g_gx);
    float* meanp; cudaGetSymbolAddress((void**)&meanp, g_mean);

    cudaFuncSetAttribute(mgemm<EPI_NONE>,       cudaFuncAttributeMaxDynamicSharedMemorySize, GEMM_SMEM);
    cudaFuncSetAttribute(mgemm<EPI_RESID>,      cudaFuncAttributeMaxDynamicSharedMemorySize, GEMM_SMEM);
    cudaFuncSetAttribute(mgemm<EPI_BIAS>,       cudaFuncAttributeMaxDynamicSharedMemorySize, GEMM_SMEM);
    cudaFuncSetAttribute(mgemm<EPI_BIAS_RELU2>, cudaFuncAttributeMaxDynamicSharedMemorySize, GEMM_SMEM);
    cudaFuncSetAttribute(mgemm<EPI_BIAS_SIG>,   cudaFuncAttributeMaxDynamicSharedMemorySize, GEMM_SMEM);

    float* B0 = buf + 0ull * NELEM;  // xx    -> kffn
    float* B1 = buf + 1ull * NELEM;  // xm    -> h
    float* B2 = buf + 2ull * NELEM;  // r     -> rg    -> fr
    float* B3 = buf + 3ull * NELEM;  // k     -> u     -> pre2
    float* B4 = buf + 4ull * NELEM;  // v     -> states
    float* B5 = buf + 5ull * NELEM;  // a     -> pre1
    float* B6 = buf + 6ull * NELEM;  // b     -> x2
    float* B7 = buf + 7ull * NELEM;  // g     -> xx2

    const int grid_e = (int)(NELEM / 256);
    dim3 gg(DD / 256, ROWS / 128);   // (4, 128)

    // 1. LN1 + time mix
    ln_kernel<<<ROWS, 256>>>(x, ln1_w, ln1_b, B0);
    xm_kernel<<<grid_e, 256>>>(B0, B1);

    // 2. six projections (tf32 mma.sync)
    mgemm<EPI_NONE><<<gg, 256, GEMM_SMEM>>>(B1, Wr, B2, nullptr, ROWS, DD, DD);
    mgemm<EPI_NONE><<<gg, 256, GEMM_SMEM>>>(B1, Wk, B3, nullptr, ROWS, DD, DD);
    mgemm<EPI_NONE><<<gg, 256, GEMM_SMEM>>>(B1, Wv, B4, nullptr, ROWS, DD, DD);
    mgemm<EPI_NONE><<<gg, 256, GEMM_SMEM>>>(B1, Wg, B7, nullptr, ROWS, DD, DD);
    mgemm<EPI_NONE><<<gg, 256, GEMM_SMEM>>>(B1, Wa, B5, nullptr, ROWS, DD, DD);
    mgemm<EPI_NONE><<<gg, 256, GEMM_SMEM>>>(B1, Wb, B6, nullptr, ROWS, DD, DD);

    // 3. u = k*v + a*b, rg = sigmoid(r)*sigmoid(g)
    fuse1_kernel<<<grid_e, 256>>>(B2, B7, B3, B4, B5, B6, B3, B2);

    // 4. decay scan
    scan_kernel<<<32, 256>>>(B3, state, decay, B4, out_state);

    // 5. GroupNorm * rg
    gnorm_kernel<<<ROWS, 256>>>(B4, B2, gn_w, gn_b, B5);

    // 6. mixed projection + residual -> x2
    mgemm<EPI_RESID><<<gg, 256, GEMM_SMEM>>>(B5, Wout, B6, x, ROWS, DD, DD);

    // 7. LN2
    ln_kernel<<<ROWS, 256>>>(B6, ln2_w, ln2_b, B7);

    // 8. FFN key: relu^2(xx2 @ Wfk + bfk)
    mgemm<EPI_BIAS_RELU2><<<gg, 256, GEMM_SMEM>>>(B7, Wfk, B0, bfk, ROWS, FFN, DD);

    // 9. h = kffn @ Wfv + bfv
    mgemm<EPI_BIAS><<<gg, 256, GEMM_SMEM>>>(B0, Wfv, B1, bfv, ROWS, DD, FFN);

    // 10. fr = sigmoid(xx2 @ Wfr + bfr)
    mgemm<EPI_BIAS_SIG><<<gg, 256, GEMM_SMEM>>>(B7, Wfr, B2, bfr, ROWS, DD, DD);

    // 11. GRN stats
    grn_gx_kernel<<<32, 256>>>(B1, gxp);
    grn_mean_kernel<<<8, 256>>>(gxp, meanp);

    // 12. pre2 = fr * ffn_hidden
    pre2_kernel<<<grid_e, 256>>>(B2, B1, gxp, meanp, grn_g, grn_b, B3);

    // 13. final projection + residual -> output x
    mgemm<EPI_RESID><<<gg, 256, GEMM_SMEM>>>(B3, Wffnout, out_x, B6, ROWS, DD, DD);
}

// round 5
// speedup vs baseline: 3.5092x; 1.0693x over previous
#include <cuda_runtime.h>
#include <math.h>
#include <stdint.h>

#define BB 8
#define TT 2048
#define DD 1024
#define FFN 1024
#define ROWS (BB*TT)                 // 16384
#define NELEM ((size_t)ROWS*DD)      // 16777216

// scratch (static device allocation)
__device__ float g_buf[8ull * 16777216ull];   // 8 x 64MB activation buffers
__device__ float g_wts[11ull * 1048576ull];   // pre-rounded tf32 weights
__device__ float g_gx[BB * DD];
__device__ float g_mean[BB];
__device__ float g_carry[BB * 16 * DD];       // chunk-end local scans
__device__ float g_pref[BB * 16 * DD];        // incoming state per chunk
__device__ float g_part[BB * 16 * DD];        // GRN partial sums
__device__ float g_wpow[128 * DD];            // w^(tl+1) table

// ===========================================================================
// helpers
// ===========================================================================
__device__ __forceinline__ uint32_t smem_u32(const void* p) {
    uint32_t a;
    asm("{ .reg .u64 t; cvta.to.shared.u64 t, %1; cvt.u32.u64 %0, t; }"
        : "=r"(a) : "l"(p));
    return a;
}

__device__ __forceinline__ void cp16(uint32_t dst, const void* src) {
    asm volatile("cp.async.cg.shared.global [%0], [%1], 16;"
                 :: "r"(dst), "l"(src));
}

__device__ __forceinline__ float rnd(float x) {   // round f32 -> canonical tf32
    uint32_t y;
    asm("cvt.rna.tf32.f32 %0, %1;" : "=r"(y) : "f"(x));
    return __uint_as_float(y);
}

__device__ __forceinline__ void mma8(float* d, const uint32_t* a,
                                     uint32_t b0, uint32_t b1) {
    asm("mma.sync.aligned.m16n8k8.row.col.f32.tf32.tf32.f32 "
        "{%0,%1,%2,%3}, {%4,%5,%6,%7}, {%8,%9}, {%0,%1,%2,%3};"
        : "+f"(d[0]), "+f"(d[1]), "+f"(d[2]), "+f"(d[3])
        : "r"(a[0]), "r"(a[1]), "r"(a[2]), "r"(a[3]), "r"(b0), "r"(b1));
}

// ===========================================================================
// unified tf32 mma.sync GEMM, runtime multi-weight batching.
// CTA tile 128M x 256N, k-stage 32, 3-stage cp.async pipeline, 256 threads.
// grid.x = 4*nW (4 n-tiles per weight), grid.y = M/128.
// ===========================================================================
enum { EPI_NONE = 0, EPI_RESID = 1, EPI_BIAS = 2, EPI_BIAS_RELU2 = 3, EPI_BIAS_SIG = 4 };

struct GemmCfg {
    float* out[6];
    const float* aux[6];   // residual (full) or bias (row) pointer
    int widx[6];           // index into g_wts (1M floats each)
    int epi[6];
};

#define A_ST 4096            // floats per A stage (128x32)
#define B_ST 8192            // floats per B stage (32x256)
#define GEMM_SMEM 147456     // 3*(A_ST+B_ST)*4 bytes

__device__ __forceinline__ void load_stage(
    const float* __restrict__ A, const float* __restrict__ W,
    int K, int N, int m0, int n0, uint32_t a_base, uint32_t b_base,
    int kc, int tid)
{
#pragma unroll
    for (int i = 0; i < 4; ++i) {
        int chunk = i * 256 + tid;
        int m = chunk >> 3, k4 = chunk & 7;
        const float* src = A + (size_t)(m0 + m) * K + kc + k4 * 4;
        cp16(a_base + (uint32_t)(m * 8 + (k4 ^ (m & 7))) * 16u, src);
    }
#pragma unroll
    for (int i = 0; i < 8; ++i) {
        int chunk = i * 256 + tid;
        int k = chunk >> 6, n4 = chunk & 63;
        const float* src = W + (size_t)(kc + k) * N + n0 + n4 * 4;
        cp16(b_base + (uint32_t)(k * 64 + (n4 ^ ((k & 3) << 1))) * 16u, src);
    }
    asm volatile("cp.async.commit_group;");
}

__global__ __launch_bounds__(256, 1) void mgemm_n(
    const float* __restrict__ A, const float* __restrict__ Wbase,
    GemmCfg cfg, int M, int N, int K)
{
    extern __shared__ float sm[];
    float* As = sm;
    float* Bs = sm + 3 * A_ST;

    const int tid = threadIdx.x;
    const int w = tid >> 5, lane = tid & 31;
    const int wm = w & 1, wn = w >> 1;
    const int r = lane >> 2, c = lane & 3;
    const int slot = blockIdx.x >> 2;
    const int m0 = blockIdx.y * 128;
    const int n0 = (blockIdx.x & 3) * 256;

    const float* W = Wbase + ((size_t)cfg.widx[slot] << 20);
    float* C = cfg.out[slot];
    const float* X = cfg.aux[slot];
    const int epi = cfg.epi[slot];

    uint32_t a_sb = smem_u32(As);
    uint32_t b_sb = smem_u32(Bs);

    float acc[4][8][4];
#pragma unroll
    for (int mt = 0; mt < 4; ++mt)
#pragma unroll
        for (int nt = 0; nt < 8; ++nt)
#pragma unroll
            for (int i = 0; i < 4; ++i) acc[mt][nt][i] = 0.f;

    const int NCH = K >> 5;

    load_stage(A, W, K, N, m0, n0, a_sb, b_sb, 0, tid);
    load_stage(A, W, K, N, m0, n0, a_sb + A_ST * 4, b_sb + B_ST * 4, 32, tid);

    for (int ch = 0; ch < NCH; ++ch) {
        asm volatile("cp.async.wait_group 1;");
        __syncthreads();

        const int p = ch % 3;
        const uint32_t* Ap = (const uint32_t*)(As + p * A_ST);
        const uint32_t* Bp = (const uint32_t*)(Bs + p * B_ST);

#pragma unroll
        for (int ks = 0; ks < 4; ++ks) {
            const int k0 = ks * 8;
            const int kc0 = (k0 + c) ^ (r << 2);
            const int kc4 = (k0 + c + 4) ^ (r << 2);
            uint32_t a[4][4];
#pragma unroll
            for (int mt = 0; mt < 4; ++mt) {
                int base = (wm * 64 + mt * 16 + r) * 32;
                a[mt][0] = Ap[base + kc0];
                a[mt][1] = Ap[base + 256 + kc0];   // +8 rows
                a[mt][2] = Ap[base + kc4];
                a[mt][3] = Ap[base + 256 + kc4];
            }
#pragma unroll
            for (int nt = 0; nt < 8; ++nt) {
                int nsw = (wn * 64 + nt * 8 + r) ^ (c << 3);
                uint32_t b0 = Bp[(k0 + c) * 256 + nsw];
                uint32_t b1 = Bp[(k0 + c + 4) * 256 + nsw];
#pragma unroll
                for (int mt = 0; mt < 4; ++mt)
                    mma8(acc[mt][nt], a[mt], b0, b1);
            }
        }

        const int nc = ch + 2;
        if (nc < NCH) {
            load_stage(A, W, K, N, m0, n0,
                       a_sb + (uint32_t)(nc % 3) * A_ST * 4,
                       b_sb + (uint32_t)(nc % 3) * B_ST * 4,
                       nc * 32, tid);
        } else {
            asm volatile("cp.async.commit_group;");
        }
    }

    // epilogue
#pragma unroll
    for (int mt = 0; mt < 4; ++mt) {
#pragma unroll
        for (int nt = 0; nt < 8; ++nt) {
            int row = m0 + wm * 64 + mt * 16 + r;
            int col = n0 + wn * 64 + nt * 8 + 2 * c;
#pragma unroll
            for (int h = 0; h < 2; ++h) {
                int rr = row + h * 8;
                float v0 = acc[mt][nt][h * 2 + 0];
                float v1 = acc[mt][nt][h * 2 + 1];
                size_t gi = (size_t)rr * N + col;
                if (epi == EPI_RESID) {
                    v0 += X[gi]; v1 += X[gi + 1];
                } else if (epi == EPI_BIAS) {
                    v0 += X[col]; v1 += X[col + 1];
                } else if (epi == EPI_BIAS_RELU2) {
                    float t0 = v0 + X[col];     t0 = t0 > 0.f ? t0 : 0.f;
                    float t1 = v1 + X[col + 1]; t1 = t1 > 0.f ? t1 : 0.f;
                    v0 = rnd(t0 * t0); v1 = rnd(t1 * t1);   // feeds GEMM
                } else if (epi == EPI_BIAS_SIG) {
                    v0 = 1.f / (1.f + expf(-(v0 + X[col])));
                    v1 = 1.f / (1.f + expf(-(v1 + X[col + 1])));
                }
                float2 o; o.x = v0; o.y = v1;
                *(float2*)(C + gi) = o;
            }
        }
    }
}

// ===========================================================================
// weight pre-rounding (11 x 1M floats -> tf32-canonical copies)
// ===========================================================================
struct WPtrs { const float* p[11]; };

__global__ void roundw_kernel(WPtrs wp, float* __restrict__ dst)
{
    size_t idx = (size_t)blockIdx.x * 256 + threadIdx.x;
    int wi = (int)(idx >> 20);
    int off = (int)(idx & 1048575u);
    dst[idx] = rnd(wp.p[wi][off]);
}

// w^(tl+1) table: wpow[tl*1024+d] = exp(-(tl+1)*exp(decay[d]))
__global__ void wpow_kernel(const float* __restrict__ decay, float* __restrict__ wpow)
{
    int idx = blockIdx.x * 256 + threadIdx.x;   // 131072
    int tl = idx >> 10, d = idx & 1023;
    wpow[idx] = expf(-(float)(tl + 1) * expf(decay[d]));
}

// ===========================================================================
// LayerNorm (templated: round output for GEMM consumers)
// ===========================================================================
template <int RND>
__global__ __launch_bounds__(256) void ln_kernel(
    const float* __restrict__ x, const float* __restrict__ w,
    const float* __restrict__ b, float* __restrict__ out)
{
    int row = blockIdx.x;
    const float* xr = x + (size_t)row * DD;
    float* orow = out + (size_t)row * DD;
    float v[4];
    float s = 0.f, ss = 0.f;
#pragma unroll
    for (int i = 0; i < 4; i++) {
        v[i] = xr[threadIdx.x + i * 256];
        s += v[i];
        ss += v[i] * v[i];
    }
#pragma unroll
    for (int o = 16; o > 0; o >>= 1) {
        s  += __shfl_xor_sync(0xffffffffu, s,  o);
        ss += __shfl_xor_sync(0xffffffffu, ss, o);
    }
    __shared__ float reds[8], redss[8];
    __shared__ float smean, sinv;
    int warp = threadIdx.x >> 5, lane = threadIdx.x & 31;
    if (lane == 0) { reds[warp] = s; redss[warp] = ss; }
    __syncthreads();
    if (threadIdx.x == 0) {
        float ts = 0.f, tss = 0.f;
#pragma unroll
        for (int i = 0; i < 8; i++) { ts += reds[i]; tss += redss[i]; }
        float mean = ts * (1.f / 1024.f);
        float var = tss * (1.f / 1024.f) - mean * mean;
        smean = mean;
        sinv = rsqrtf(var + 1e-5f);
    }
    __syncthreads();
    float mean = smean, inv = sinv;
#pragma unroll
    for (int i = 0; i < 4; i++) {
        int cc = threadIdx.x + i * 256;
        float o = (v[i] - mean) * inv * w[cc] + b[cc];
        orow[cc] = RND ? rnd(o) : o;
    }
}

__global__ void xm_kernel(const float* __restrict__ xx, float* __restrict__ xm)
{
    size_t idx = (size_t)blockIdx.x * blockDim.x + threadIdx.x;
    if (idx >= NELEM) return;
    size_t row = idx >> 10;
    int tl = (int)(row & 2047);
    float prev = tl ? xx[idx - DD] : 0.f;
    xm[idx] = rnd(0.5f * (xx[idx] + prev));    // feeds GEMMs only
}

__global__ void fuse1_kernel(
    const float* __restrict__ r, const float* __restrict__ g,
    const float* __restrict__ k, const float* __restrict__ v,
    const float* __restrict__ a, const float* __restrict__ b,
    float* __restrict__ u, float* __restrict__ rg)
{
    size_t idx = (size_t)blockIdx.x * blockDim.x + threadIdx.x;
    if (idx >= NELEM) return;
    float kv = k[idx] * v[idx];
    float ab = a[idx] * b[idx];
    float sr = 1.f / (1.f + expf(-r[idx]));
    float sg = 1.f / (1.f + expf(-g[idx]));
    u[idx] = kv + ab;
    rg[idx] = sr * sg;
}

// ===========================================================================
// chunked decay scan: T=2048 split into 16 chunks of 128
// ===========================================================================
__global__ void scan_part1(const float* __restrict__ u,
                           const float* __restrict__ decay,
                           float* __restrict__ l, float* __restrict__ carry)
{
    int gb = blockIdx.x;                 // 512 blocks
    int d = (gb & 3) * 256 + threadIdx.x;
    int chunk = (gb >> 2) & 15;
    int b = gb >> 6;
    float w = expf(-expf(decay[d]));
    float s = 0.f;
    size_t idx = ((size_t)b * TT + chunk * 128) * DD + d;
#pragma unroll 4
    for (int i = 0; i < 128; ++i, idx += DD) {
        s = fmaf(s, w, u[idx]);
        l[idx] = s;
    }
    carry[(b * 16 + chunk) * 1024 + d] = s;
}

__global__ void scan_part2(const float* __restrict__ carry,
                           const float* __restrict__ state0,
                           const float* __restrict__ wpow,
                           float* __restrict__ pref,
                           float* __restrict__ final_state)
{
    int t = blockIdx.x * 256 + threadIdx.x;   // 8192
    int b = t >> 10, d = t & 1023;
    float wL = wpow[127 * 1024 + d];          // w^128
    float S = state0[t];
#pragma unroll
    for (int c = 0; c < 16; ++c) {
        pref[(b * 16 + c) * 1024 + d] = S;
        S = fmaf(wL, S, carry[(b * 16 + c) * 1024 + d]);
    }
    final_state[t] = S;
}

// GroupNorm fused with scan combine: s = l + w^(tl+1)*pref
__global__ __launch_bounds__(256) void gnorm_kernel(
    const float* __restrict__ l, const float* __restrict__ rg,
    const float* __restrict__ gw, const float* __restrict__ gb_,
    const float* __restrict__ wpow, const float* __restrict__ pref,
    float* __restrict__ out)
{
    int row = blockIdx.x;
    int b = row >> 11, t = row & 2047;
    int tl = t & 127, ch = t >> 7;
    const float* wp = wpow + tl * 1024;
    const float* pf = pref + (b * 16 + ch) * 1024;
    int warp = threadIdx.x >> 5, lane = threadIdx.x & 31;
    size_t base = (size_t)row * DD;
#pragma unroll
    for (int g = warp; g < 32; g += 8) {
        int cc = g * 32 + lane;
        float v = fmaf(wp[cc], pf[cc], l[base + cc]);
        float s = v, ss = v * v;
#pragma unroll
        for (int o = 16; o > 0; o >>= 1) {
            s  += __shfl_xor_sync(0xffffffffu, s,  o);
            ss += __shfl_xor_sync(0xffffffffu, ss, o);
        }
        float mean = s * (1.f / 32.f);
        float var = ss * (1.f / 32.f) - mean * mean;
        float inv = rsqrtf(var + 1e-5f);
        out[base + cc] = rnd(((v - mean) * inv * gw[cc] + gb_[cc]) * rg[base + cc]);
    }
}

// ===========================================================================
// GRN: chunked partial sums of h^2, then sqrt + mean
// ===========================================================================
__global__ void grn_part(const float* __restrict__ h, float* __restrict__ part)
{
    int gb = blockIdx.x;                 // 512 blocks
    int d = (gb & 3) * 256 + threadIdx.x;
    int chunk = (gb >> 2) & 15;
    int b = gb >> 6;
    size_t idx = ((size_t)b * TT + chunk * 128) * DD + d;
    float s = 0.f;
#pragma unroll 4
    for (int i = 0; i < 128; ++i, idx += DD) {
        float v = h[idx];
        s = fmaf(v, v, s);
    }
    part[(b * 16 + chunk) * 1024 + d] = s;
}

__global__ __launch_bounds__(256) void grn_mean(
    const float* __restrict__ part, float* __restrict__ gx, float* __restrict__ mean)
{
    int b = blockIdx.x;
    float local = 0.f;
    for (int i = threadIdx.x; i < 1024; i += 256) {
        float s = 0.f;
#pragma unroll
        for (int c = 0; c < 16; ++c) s += part[(b * 16 + c) * 1024 + i];
        float g = sqrtf(s);
        gx[b * 1024 + i] = g;
        local += g;
    }
#pragma unroll
    for (int o = 16; o > 0; o >>= 1) local += __shfl_xor_sync(0xffffffffu, local, o);
    __shared__ float red[8];
    int warp = threadIdx.x >> 5, lane = threadIdx.x & 31;
    if (lane == 0) red[warp] = local;
    __syncthreads();
    if (threadIdx.x == 0) {
        float t = 0.f;
#pragma unroll
        for (int i = 0; i < 8; i++) t += red[i];
        mean[b] = t * (1.f / 1024.f);
    }
}

__global__ void pre2_kernel(
    const float* __restrict__ fr, const float* __restrict__ h,
    const float* __restrict__ gx, const float* __restrict__ mean,
    const float* __restrict__ gamma, const float* __restrict__ beta,
    float* __restrict__ out)
{
    size_t idx = (size_t)blockIdx.x * blockDim.x + threadIdx.x;
    if (idx >= NELEM) return;
    int d = (int)(idx & 1023);
    size_t row = idx >> 10;
    int bb = (int)(row >> 11);
    float nx = gx[bb * DD + d] / (mean[bb] + 1e-6f);
    float hv = h[idx];
    float hidden = fmaf(hv, gamma[d] * nx, beta[d]) + hv;
    out[idx] = rnd(fr[idx] * hidden);          // feeds final GEMM
}

// ===========================================================================
// launch
// ===========================================================================
extern "C" void kernel_launch(void* const* d_in, const int* in_sizes, int n_in,
                              void* d_out, int out_size)
{
    const float* x       = (const float*)d_in[0];
    const float* state   = (const float*)d_in[1];
    const float* ln1_w   = (const float*)d_in[2];
    const float* ln1_b   = (const float*)d_in[3];
    const float* ln2_w   = (const float*)d_in[4];
    const float* ln2_b   = (const float*)d_in[5];
    const float* gn_w    = (const float*)d_in[6];
    const float* gn_b    = (const float*)d_in[7];
    const float* grn_g   = (const float*)d_in[8];
    const float* grn_b   = (const float*)d_in[9];
    const float* decay   = (const float*)d_in[10];
    const float* Wr      = (const float*)d_in[11];
    const float* Wk      = (const float*)d_in[12];
    const float* Wv      = (const float*)d_in[13];
    const float* Wg      = (const float*)d_in[14];
    const float* Wa      = (const float*)d_in[15];
    const float* Wb      = (const float*)d_in[16];
    const float* Wout    = (const float*)d_in[17];
    const float* Wffnout = (const float*)d_in[18];
    const float* Wfk     = (const float*)d_in[19];
    const float* bfk     = (const float*)d_in[20];
    const float* Wfv     = (const float*)d_in[21];
    const float* bfv     = (const float*)d_in[22];
    const float* Wfr     = (const float*)d_in[23];
    const float* bfr     = (const float*)d_in[24];

    float* out_x = (float*)d_out;
    float* out_state = out_x + NELEM;

    float* buf;    cudaGetSymbolAddress((void**)&buf, g_buf);
    float* wts;    cudaGetSymbolAddress((void**)&wts, g_wts);
    float* gxp;    cudaGetSymbolAddress((void**)&gxp, g_gx);
    float* meanp;  cudaGetSymbolAddress((void**)&meanp, g_mean);
    float* carryp; cudaGetSymbolAddress((void**)&carryp, g_carry);
    float* prefp;  cudaGetSymbolAddress((void**)&prefp, g_pref);
    float* partp;  cudaGetSymbolAddress((void**)&partp, g_part);
    float* wpowp;  cudaGetSymbolAddress((void**)&wpowp, g_wpow);

    cudaFuncSetAttribute(mgemm_n, cudaFuncAttributeMaxDynamicSharedMemorySize, GEMM_SMEM);

    float* B0 = buf + 0ull * NELEM;  // xx    -> kffn
    float* B1 = buf + 1ull * NELEM;  // xm    -> h
    float* B2 = buf + 2ull * NELEM;  // r     -> rg    -> fr
    float* B3 = buf + 3ull * NELEM;  // k     -> u     -> pre2
    float* B4 = buf + 4ull * NELEM;  // v     -> local scans
    float* B5 = buf + 5ull * NELEM;  // a     -> pre1
    float* B6 = buf + 6ull * NELEM;  // b     -> x2
    float* B7 = buf + 7ull * NELEM;  // g     -> xx2

    const int grid_e = (int)(NELEM / 256);

    // 0. weight pre-rounding + decay power table (independent prep)
    WPtrs wp;
    wp.p[0] = Wr; wp.p[1] = Wk; wp.p[2] = Wv; wp.p[3] = Wg; wp.p[4] = Wa;
    wp.p[5] = Wb; wp.p[6] = Wout; wp.p[7] = Wffnout; wp.p[8] = Wfk;
    wp.p[9] = Wfv; wp.p[10] = Wfr;
    roundw_kernel<<<11 * 4096, 256>>>(wp, wts);
    wpow_kernel<<<512, 256>>>(decay, wpowp);

    // 1. LN1 + time mix
    ln_kernel<0><<<ROWS, 256>>>(x, ln1_w, ln1_b, B0);
    xm_kernel<<<grid_e, 256>>>(B0, B1);

    // 2. six projections, one launch
    {
        GemmCfg c = {};
        float* outs[6] = {B2, B3, B4, B7, B5, B6};
        for (int i = 0; i < 6; i++) { c.out[i] = outs[i]; c.widx[i] = i; c.epi[i] = EPI_NONE; c.aux[i] = nullptr; }
        dim3 gg(24, 128);
        mgemm_n<<<gg, 256, GEMM_SMEM>>>(B1, wts, c, ROWS, DD, DD);
    }

    // 3. u = k*v + a*b, rg = sigmoid(r)*sigmoid(g)
    fuse1_kernel<<<grid_e, 256>>>(B2, B7, B3, B4, B5, B6, B3, B2);

    // 4. chunked decay scan
    scan_part1<<<512, 256>>>(B3, decay, B4, carryp);
    scan_part2<<<32, 256>>>(carryp, state, wpowp, prefp, out_state);

    // 5. GroupNorm (fused scan combine) * rg
    gnorm_kernel<<<ROWS, 256>>>(B4, B2, gn_w, gn_b, wpowp, prefp, B5);

    // 6. mixed projection + residual -> x2
    {
        GemmCfg c = {};
        c.out[0] = B6; c.aux[0] = x; c.widx[0] = 6; c.epi[0] = EPI_RESID;
        dim3 gg(4, 128);
        mgemm_n<<<gg, 256, GEMM_SMEM>>>(B5, wts, c, ROWS, DD, DD);
    }

    // 7. LN2 (rounded: feeds GEMMs only)
    ln_kernel<1><<<ROWS, 256>>>(B6, ln2_w, ln2_b, B7);

    // 8+10. Wfk (relu^2) and Wfr (sigmoid), one launch
    {
        GemmCfg c = {};
        c.out[0] = B0; c.aux[0] = bfk; c.widx[0] = 8;  c.epi[0] = EPI_BIAS_RELU2;
        c.out[1] = B2; c.aux[1] = bfr; c.widx[1] = 10; c.epi[1] = EPI_BIAS_SIG;
        dim3 gg(8, 128);
        mgemm_n<<<gg, 256, GEMM_SMEM>>>(B7, wts, c, ROWS, DD, DD);
    }

    // 9. h = kffn @ Wfv + bfv
    {
        GemmCfg c = {};
        c.out[0] = B1; c.aux[0] = bfv; c.widx[0] = 9; c.epi[0] = EPI_BIAS;
        dim3 gg(4, 128);
        mgemm_n<<<gg, 256, GEMM_SMEM>>>(B0, wts, c, ROWS, DD, FFN);
    }

    // 11. GRN stats (chunked, deterministic)
    grn_part<<<512, 256>>>(B1, partp);
    grn_mean<<<8, 256>>>(partp, gxp, meanp);

    // 12. pre2 = fr * ffn_hidden
    pre2_kernel<<<grid_e, 256>>>(B2, B1, gxp, meanp, grn_g, grn_b, B3);

    // 13. final projection + residual -> output x
    {
        GemmCfg c = {};
        c.out[0] = out_x; c.aux[0] = B6; c.widx[0] = 7; c.epi[0] = EPI_RESID;
        dim3 gg(4, 128);
        mgemm_n<<<gg, 256, GEMM_SMEM>>>(B3, wts, c, ROWS, DD, DD);
    }
}